// round 1
// baseline (speedup 1.0000x reference)
#include <cuda_runtime.h>
#include <math.h>

#define Bq   16
#define Nq   1024
#define Cq   768
#define Hq   12
#define HD   64
#define BH   (Bq*Hq)        // 192
#define MROWS (Bq*Nq)       // 16384

// ---- scratch (no allocs allowed) ----
__device__ float g_q[BH * Nq * HD];     // [bh][tok][d]
__device__ float g_k[BH * Nq * HD];
__device__ float g_v[BH * Nq * HD];
__device__ float g_att[MROWS * Cq];     // [b*N + tok][h*64 + d]

// =====================================================================
// GEMM 1: qkv = x @ W_qkv + b_qkv, scattered into g_q/g_k/g_v
// 128x128x8 tile, 256 threads, 8x8 per thread
// =====================================================================
__global__ __launch_bounds__(256) void qkv_gemm(const float* __restrict__ x,
                                                const float* __restrict__ W,
                                                const float* __restrict__ bias)
{
    __shared__ float As[8][128];
    __shared__ float Bs[8][128];
    const int K = Cq, Nn = 3 * Cq;
    int tid  = threadIdx.x;
    int rowA = tid >> 1, kA = (tid & 1) << 2;
    int kB   = tid >> 5, colB = (tid & 31) << 2;
    const float* xg = x + (blockIdx.y * 128 + rowA) * K + kA;
    const float* wg = W + kB * Nn + blockIdx.x * 128 + colB;
    int ty = tid >> 4, tx = tid & 15;
    float acc[8][8] = {};

    for (int k0 = 0; k0 < K; k0 += 8) {
        float4 av = *(const float4*)(xg + k0);
        As[kA + 0][rowA] = av.x; As[kA + 1][rowA] = av.y;
        As[kA + 2][rowA] = av.z; As[kA + 3][rowA] = av.w;
        *(float4*)&Bs[kB][colB] = *(const float4*)(wg + (size_t)k0 * Nn);
        __syncthreads();
        #pragma unroll
        for (int k = 0; k < 8; k++) {
            float a[8], b[8];
            *(float4*)(a)     = *(const float4*)&As[k][ty * 8];
            *(float4*)(a + 4) = *(const float4*)&As[k][ty * 8 + 4];
            *(float4*)(b)     = *(const float4*)&Bs[k][tx * 8];
            *(float4*)(b + 4) = *(const float4*)&Bs[k][tx * 8 + 4];
            #pragma unroll
            for (int i = 0; i < 8; i++)
                #pragma unroll
                for (int j = 0; j < 8; j++)
                    acc[i][j] = fmaf(a[i], b[j], acc[i][j]);
        }
        __syncthreads();
    }

    int gm0 = blockIdx.y * 128 + ty * 8;
    int gn0 = blockIdx.x * 128 + tx * 8;
    #pragma unroll
    for (int i = 0; i < 8; i++) {
        int gm = gm0 + i;
        int b_ = gm >> 10, tok = gm & 1023;
        #pragma unroll
        for (int j = 0; j < 8; j++) {
            int gn = gn0 + j;
            float v = acc[i][j] + bias[gn];
            int s   = gn / Cq;
            int rem = gn - s * Cq;
            int h = rem >> 6, d = rem & 63;
            float* dst = (s == 0) ? g_q : ((s == 1) ? g_k : g_v);
            dst[((b_ * Hq + h) << 16) + (tok << 6) + d] = v;
        }
    }
}

// =====================================================================
// RoPE (in place on g_q / g_k). Reference semantics:
// out[j]    = t[j]   *cos(p*inv[j/2])      - t[j+16]*sin(p*inv[j/2])
// out[j+16] = t[j+16]*cos(p*inv[8+j/2])    + t[j]   *sin(p*inv[8+j/2])
// per 32-dim half; half 0 uses pos_h, half 1 uses pos_w.
// =====================================================================
__global__ void rope_kernel(const int* __restrict__ pos_h,
                            const int* __restrict__ pos_w)
{
    int idx = blockIdx.x * blockDim.x + threadIdx.x;
    int j    = idx & 15;
    int half = (idx >> 4) & 1;
    int tok  = (idx >> 5) & 1023;
    int rest = idx >> 15;           // 0..383
    if (rest >= 2 * BH) return;
    int bh   = rest % BH;
    int tens = rest / BH;           // 0=q, 1=k
    int b_ = bh / Hq;
    int pos = half ? pos_w[b_ * Nq + tok] : pos_h[b_ * Nq + tok];
    float fp = (float)pos;
    float* base = (tens ? g_k : g_q) + (bh << 16) + (tok << 6) + half * 32;
    float t0 = base[j], t1 = base[j + 16];
    float L = logf(10000.0f);
    float inv0 = expf(-(float)(j >> 1)       / 16.0f * L);
    float inv1 = expf(-(float)(8 + (j >> 1)) / 16.0f * L);
    float s0, c0, s1, c1;
    sincosf(fp * inv0, &s0, &c0);
    sincosf(fp * inv1, &s1, &c1);
    base[j]      = t0 * c0 - t1 * s0;
    base[j + 16] = t1 * c1 + t0 * s1;
}

// =====================================================================
// Flash attention: block = (q-tile of 64 rows, bh). 16 key tiles of 64.
// Dynamic smem: Qt[64][68] (k-major), KP[64][68] (K^T then aliased as P^T),
// Vs[64][68], red[64][17], row stats.
// =====================================================================
#define QP 68
#define ATTN_SMEM ((3 * 64 * QP + 64 * 17 + 4 * 64) * sizeof(float))

__global__ __launch_bounds__(256) void attn_kernel()
{
    extern __shared__ float sm[];
    float* Qt   = sm;                  // Qt[k*QP + r]
    float* KP   = Qt + 64 * QP;        // Kt[k*QP + c]  /  Pt[c*QP + r]
    float* Vs   = KP + 64 * QP;        // Vs[c*QP + j]
    float* red  = Vs + 64 * QP;        // [64][17]
    float* mrow = red + 64 * 17;
    float* lrow = mrow + 64;
    float* arow = lrow + 64;
    float* mnew = arow + 64;

    int tid = threadIdx.x;
    int bh  = blockIdx.y;
    int q0  = blockIdx.x * 64;
    const float* Qg = g_q + (bh << 16);
    const float* Kg = g_k + (bh << 16);
    const float* Vg = g_v + (bh << 16);
    int ty = tid >> 4, tx = tid & 15;

    for (int idx = tid; idx < 4096; idx += 256) {
        int r = idx >> 6, k = idx & 63;
        Qt[k * QP + r] = Qg[(q0 + r) * 64 + k];
    }
    if (tid < 64) { mrow[tid] = -INFINITY; lrow[tid] = 0.0f; }
    __syncthreads();

    float o[4][4] = {};

    for (int t = 0; t < 16; t++) {
        int kt0 = t * 64;
        for (int idx = tid; idx < 4096; idx += 256) {
            int c = idx >> 6, k = idx & 63;
            KP[k * QP + c] = Kg[(kt0 + c) * 64 + k];
        }
        for (int idx = tid; idx < 4096; idx += 256) {
            int c = idx >> 6, j = idx & 63;
            Vs[c * QP + j] = Vg[(kt0 + c) * 64 + j];
        }
        __syncthreads();

        // S = Q @ K^T * scale
        float s_[4][4] = {};
        #pragma unroll 16
        for (int k = 0; k < 64; k++) {
            float a[4], b[4];
            *(float4*)a = *(const float4*)&Qt[k * QP + ty * 4];
            *(float4*)b = *(const float4*)&KP[k * QP + tx * 4];
            #pragma unroll
            for (int i = 0; i < 4; i++)
                #pragma unroll
                for (int j = 0; j < 4; j++)
                    s_[i][j] = fmaf(a[i], b[j], s_[i][j]);
        }
        #pragma unroll
        for (int i = 0; i < 4; i++)
            #pragma unroll
            for (int j = 0; j < 4; j++)
                s_[i][j] *= 0.125f;

        // per-thread row-partial max -> red
        #pragma unroll
        for (int i = 0; i < 4; i++) {
            float pm = fmaxf(fmaxf(s_[i][0], s_[i][1]), fmaxf(s_[i][2], s_[i][3]));
            red[(ty * 4 + i) * 17 + tx] = pm;
        }
        __syncthreads();   // also guards: all KP (Kt) reads done

        if (tid < 64) {
            float m = -INFINITY;
            #pragma unroll
            for (int u = 0; u < 16; u++) m = fmaxf(m, red[tid * 17 + u]);
            float mo = mrow[tid];
            float mn = fmaxf(mo, m);
            mnew[tid] = mn;
            arow[tid] = expf(mo - mn);
            mrow[tid] = mn;
        }
        __syncthreads();

        // P = exp(S - m), partial row sums, store P^T into KP
        float pmat[4][4];
        #pragma unroll
        for (int i = 0; i < 4; i++) {
            int r = ty * 4 + i;
            float mn = mnew[r];
            float ps = 0.0f;
            #pragma unroll
            for (int j = 0; j < 4; j++) {
                pmat[i][j] = expf(s_[i][j] - mn);
                ps += pmat[i][j];
            }
            red[r * 17 + tx] = ps;
        }
        #pragma unroll
        for (int j = 0; j < 4; j++) {
            float4 st = make_float4(pmat[0][j], pmat[1][j], pmat[2][j], pmat[3][j]);
            *(float4*)&KP[(tx * 4 + j) * QP + ty * 4] = st;
        }
        __syncthreads();

        if (tid < 64) {
            float s = 0.0f;
            #pragma unroll
            for (int u = 0; u < 16; u++) s += red[tid * 17 + u];
            lrow[tid] = lrow[tid] * arow[tid] + s;
        }

        // O = O * alpha + P @ V
        float al[4];
        #pragma unroll
        for (int i = 0; i < 4; i++) al[i] = arow[ty * 4 + i];
        #pragma unroll
        for (int i = 0; i < 4; i++)
            #pragma unroll
            for (int j = 0; j < 4; j++)
                o[i][j] *= al[i];

        #pragma unroll 16
        for (int c = 0; c < 64; c++) {
            float4 p4 = *(const float4*)&KP[c * QP + ty * 4];
            float4 v4 = *(const float4*)&Vs[c * QP + tx * 4];
            float pa[4] = {p4.x, p4.y, p4.z, p4.w};
            float vb[4] = {v4.x, v4.y, v4.z, v4.w};
            #pragma unroll
            for (int i = 0; i < 4; i++)
                #pragma unroll
                for (int j = 0; j < 4; j++)
                    o[i][j] = fmaf(pa[i], vb[j], o[i][j]);
        }
        __syncthreads();   // before next tile overwrites KP/Vs/red
    }

    // write out: g_att[(b*1024 + q0 + r) * 768 + h*64 + col]
    int b_ = bh / Hq, h = bh % Hq;
    #pragma unroll
    for (int i = 0; i < 4; i++) {
        int r = ty * 4 + i;
        float linv = 1.0f / lrow[r];
        float4 st = make_float4(o[i][0] * linv, o[i][1] * linv,
                                o[i][2] * linv, o[i][3] * linv);
        *(float4*)&g_att[(size_t)(b_ * Nq + q0 + r) * Cq + h * 64 + tx * 4] = st;
    }
}

// =====================================================================
// GEMM 2: out = g_att @ W_proj + b_proj  (16384x768x768)
// =====================================================================
__global__ __launch_bounds__(256) void proj_gemm(const float* __restrict__ W,
                                                 const float* __restrict__ bias,
                                                 float* __restrict__ out)
{
    __shared__ float As[8][128];
    __shared__ float Bs[8][128];
    const int K = Cq, Nn = Cq;
    int tid  = threadIdx.x;
    int rowA = tid >> 1, kA = (tid & 1) << 2;
    int kB   = tid >> 5, colB = (tid & 31) << 2;
    const float* xg = g_att + (size_t)(blockIdx.y * 128 + rowA) * K + kA;
    const float* wg = W + kB * Nn + blockIdx.x * 128 + colB;
    int ty = tid >> 4, tx = tid & 15;
    float acc[8][8] = {};

    for (int k0 = 0; k0 < K; k0 += 8) {
        float4 av = *(const float4*)(xg + k0);
        As[kA + 0][rowA] = av.x; As[kA + 1][rowA] = av.y;
        As[kA + 2][rowA] = av.z; As[kA + 3][rowA] = av.w;
        *(float4*)&Bs[kB][colB] = *(const float4*)(wg + (size_t)k0 * Nn);
        __syncthreads();
        #pragma unroll
        for (int k = 0; k < 8; k++) {
            float a[8], b[8];
            *(float4*)(a)     = *(const float4*)&As[k][ty * 8];
            *(float4*)(a + 4) = *(const float4*)&As[k][ty * 8 + 4];
            *(float4*)(b)     = *(const float4*)&Bs[k][tx * 8];
            *(float4*)(b + 4) = *(const float4*)&Bs[k][tx * 8 + 4];
            #pragma unroll
            for (int i = 0; i < 8; i++)
                #pragma unroll
                for (int j = 0; j < 8; j++)
                    acc[i][j] = fmaf(a[i], b[j], acc[i][j]);
        }
        __syncthreads();
    }

    int gm0 = blockIdx.y * 128 + ty * 8;
    int gn0 = blockIdx.x * 128 + tx * 8;
    float bi[8];
    *(float4*)(bi)     = *(const float4*)&bias[gn0];
    *(float4*)(bi + 4) = *(const float4*)&bias[gn0 + 4];
    #pragma unroll
    for (int i = 0; i < 8; i++) {
        float4 v0 = make_float4(acc[i][0] + bi[0], acc[i][1] + bi[1],
                                acc[i][2] + bi[2], acc[i][3] + bi[3]);
        float4 v1 = make_float4(acc[i][4] + bi[4], acc[i][5] + bi[5],
                                acc[i][6] + bi[6], acc[i][7] + bi[7]);
        float* row = out + (size_t)(gm0 + i) * Nn + gn0;
        *(float4*)(row)     = v0;
        *(float4*)(row + 4) = v1;
    }
}

// =====================================================================
extern "C" void kernel_launch(void* const* d_in, const int* in_sizes, int n_in,
                              void* d_out, int out_size)
{
    const float* x      = (const float*)d_in[0];
    const float* W_qkv  = (const float*)d_in[1];
    const float* b_qkv  = (const float*)d_in[2];
    const float* W_proj = (const float*)d_in[3];
    const float* b_proj = (const float*)d_in[4];
    const int*   pos_h  = (const int*)d_in[5];
    const int*   pos_w  = (const int*)d_in[6];
    float*       out    = (float*)d_out;

    cudaFuncSetAttribute(attn_kernel,
                         cudaFuncAttributeMaxDynamicSharedMemorySize,
                         (int)ATTN_SMEM);

    qkv_gemm<<<dim3(18, 128), 256>>>(x, W_qkv, b_qkv);
    rope_kernel<<<(2 * BH * Nq * 32) / 256, 256>>>(pos_h, pos_w);
    attn_kernel<<<dim3(16, 192), 256, ATTN_SMEM>>>();
    proj_gemm<<<dim3(6, 128), 256>>>(W_proj, b_proj, out);
}

// round 7
// speedup vs baseline: 1.0498x; 1.0498x over previous
#include <cuda_runtime.h>
#include <math.h>

#define Bq   16
#define Nq   1024
#define Cq   768
#define Hq   12
#define HD   64
#define BH   (Bq*Hq)        // 192
#define MROWS (Bq*Nq)       // 16384

// ---- scratch (no allocs allowed) ----
__device__ float g_q[BH * Nq * HD];     // [bh][tok][d]
__device__ float g_k[BH * Nq * HD];
__device__ float g_v[BH * Nq * HD];
__device__ float g_att[MROWS * Cq];     // [b*N + tok][h*64 + d]

// =====================================================================
// GEMM 1: qkv = x @ W_qkv + b_qkv, scattered into g_q/g_k/g_v
// 128x128x8 tile, 256 threads, 8x8 per thread. Double-buffered smem.
// =====================================================================
__global__ __launch_bounds__(256) void qkv_gemm(const float* __restrict__ x,
                                                const float* __restrict__ W,
                                                const float* __restrict__ bias)
{
    __shared__ float As[2][8][128];
    __shared__ float Bs[2][8][128];
    const int K = Cq, Nn = 3 * Cq;
    int tid  = threadIdx.x;
    int rowA = tid >> 1, kA = (tid & 1) << 2;
    int kB   = tid >> 5, colB = (tid & 31) << 2;
    const float* xg = x + (blockIdx.y * 128 + rowA) * K + kA;
    const float* wg = W + kB * Nn + blockIdx.x * 128 + colB;
    int ty = tid >> 4, tx = tid & 15;
    float acc[8][8] = {};

    // preload chunk 0
    float4 av = *(const float4*)(xg);
    float4 bv = *(const float4*)(wg);
    As[0][kA + 0][rowA] = av.x; As[0][kA + 1][rowA] = av.y;
    As[0][kA + 2][rowA] = av.z; As[0][kA + 3][rowA] = av.w;
    *(float4*)&Bs[0][kB][colB] = bv;
    __syncthreads();

    const int NCH = K / 8;   // 96
    for (int ch = 0; ch < NCH; ch++) {
        const int cur = ch & 1;
        if (ch + 1 < NCH) {
            av = *(const float4*)(xg + (ch + 1) * 8);
            bv = *(const float4*)(wg + (size_t)(ch + 1) * 8 * Nn);
        }
        #pragma unroll
        for (int k = 0; k < 8; k++) {
            float a[8], b[8];
            *(float4*)(a)     = *(const float4*)&As[cur][k][ty * 8];
            *(float4*)(a + 4) = *(const float4*)&As[cur][k][ty * 8 + 4];
            *(float4*)(b)     = *(const float4*)&Bs[cur][k][tx * 8];
            *(float4*)(b + 4) = *(const float4*)&Bs[cur][k][tx * 8 + 4];
            #pragma unroll
            for (int i = 0; i < 8; i++)
                #pragma unroll
                for (int j = 0; j < 8; j++)
                    acc[i][j] = fmaf(a[i], b[j], acc[i][j]);
        }
        if (ch + 1 < NCH) {
            const int nxt = cur ^ 1;
            As[nxt][kA + 0][rowA] = av.x; As[nxt][kA + 1][rowA] = av.y;
            As[nxt][kA + 2][rowA] = av.z; As[nxt][kA + 3][rowA] = av.w;
            *(float4*)&Bs[nxt][kB][colB] = bv;
        }
        __syncthreads();
    }

    int gm0 = blockIdx.y * 128 + ty * 8;
    int gn0 = blockIdx.x * 128 + tx * 8;
    #pragma unroll
    for (int i = 0; i < 8; i++) {
        int gm = gm0 + i;
        int b_ = gm >> 10, tok = gm & 1023;
        #pragma unroll
        for (int j = 0; j < 8; j++) {
            int gn = gn0 + j;
            float v = acc[i][j] + bias[gn];
            int s   = gn / Cq;
            int rem = gn - s * Cq;
            int h = rem >> 6, d = rem & 63;
            float* dst = (s == 0) ? g_q : ((s == 1) ? g_k : g_v);
            dst[((b_ * Hq + h) << 16) + (tok << 6) + d] = v;
        }
    }
}

// =====================================================================
// RoPE (in place on g_q / g_k). Reference semantics:
// out[j]    = t[j]   *cos(p*inv[j/2])      - t[j+16]*sin(p*inv[j/2])
// out[j+16] = t[j+16]*cos(p*inv[8+j/2])    + t[j]   *sin(p*inv[8+j/2])
// per 32-dim half; half 0 uses pos_h, half 1 uses pos_w.
// =====================================================================
__global__ void rope_kernel(const int* __restrict__ pos_h,
                            const int* __restrict__ pos_w)
{
    int idx = blockIdx.x * blockDim.x + threadIdx.x;
    int j    = idx & 15;
    int half = (idx >> 4) & 1;
    int tok  = (idx >> 5) & 1023;
    int rest = idx >> 15;           // 0..383
    if (rest >= 2 * BH) return;
    int bh   = rest % BH;
    int tens = rest / BH;           // 0=q, 1=k
    int b_ = bh / Hq;
    int pos = half ? pos_w[b_ * Nq + tok] : pos_h[b_ * Nq + tok];
    float fp = (float)pos;
    float* base = (tens ? g_k : g_q) + (bh << 16) + (tok << 6) + half * 32;
    float t0 = base[j], t1 = base[j + 16];
    float L = logf(10000.0f);
    float inv0 = expf(-(float)(j >> 1)       / 16.0f * L);
    float inv1 = expf(-(float)(8 + (j >> 1)) / 16.0f * L);
    float s0, c0, s1, c1;
    sincosf(fp * inv0, &s0, &c0);
    sincosf(fp * inv1, &s1, &c1);
    base[j]      = t0 * c0 - t1 * s0;
    base[j + 16] = t1 * c1 + t0 * s1;
}

// =====================================================================
// Flash attention: block = (q-tile of 64 rows, bh). 16 key tiles of 64.
// Dynamic smem: Qt[64][68] (k-major), KP[64][68] (K^T then aliased as P^T),
// Vs[64][68], red[64][17], row stats.  (identical to round-1 passing
// kernel except expf -> __expf)
// =====================================================================
#define QP 68
#define ATTN_SMEM ((3 * 64 * QP + 64 * 17 + 4 * 64) * sizeof(float))

__global__ __launch_bounds__(256) void attn_kernel()
{
    extern __shared__ float sm[];
    float* Qt   = sm;                  // Qt[k*QP + r]
    float* KP   = Qt + 64 * QP;        // Kt[k*QP + c]  /  Pt[c*QP + r]
    float* Vs   = KP + 64 * QP;        // Vs[c*QP + j]
    float* red  = Vs + 64 * QP;        // [64][17]
    float* mrow = red + 64 * 17;
    float* lrow = mrow + 64;
    float* arow = lrow + 64;
    float* mnew = arow + 64;

    int tid = threadIdx.x;
    int bh  = blockIdx.y;
    int q0  = blockIdx.x * 64;
    const float* Qg = g_q + (bh << 16);
    const float* Kg = g_k + (bh << 16);
    const float* Vg = g_v + (bh << 16);
    int ty = tid >> 4, tx = tid & 15;

    for (int idx = tid; idx < 4096; idx += 256) {
        int r = idx >> 6, k = idx & 63;
        Qt[k * QP + r] = Qg[(q0 + r) * 64 + k];
    }
    if (tid < 64) { mrow[tid] = -INFINITY; lrow[tid] = 0.0f; }
    __syncthreads();

    float o[4][4] = {};

    for (int t = 0; t < 16; t++) {
        int kt0 = t * 64;
        for (int idx = tid; idx < 4096; idx += 256) {
            int c = idx >> 6, k = idx & 63;
            KP[k * QP + c] = Kg[(kt0 + c) * 64 + k];
        }
        for (int idx = tid; idx < 4096; idx += 256) {
            int c = idx >> 6, j = idx & 63;
            Vs[c * QP + j] = Vg[(kt0 + c) * 64 + j];
        }
        __syncthreads();

        // S = Q @ K^T * scale
        float s_[4][4] = {};
        #pragma unroll 16
        for (int k = 0; k < 64; k++) {
            float a[4], b[4];
            *(float4*)a = *(const float4*)&Qt[k * QP + ty * 4];
            *(float4*)b = *(const float4*)&KP[k * QP + tx * 4];
            #pragma unroll
            for (int i = 0; i < 4; i++)
                #pragma unroll
                for (int j = 0; j < 4; j++)
                    s_[i][j] = fmaf(a[i], b[j], s_[i][j]);
        }
        #pragma unroll
        for (int i = 0; i < 4; i++)
            #pragma unroll
            for (int j = 0; j < 4; j++)
                s_[i][j] *= 0.125f;

        // per-thread row-partial max -> red
        #pragma unroll
        for (int i = 0; i < 4; i++) {
            float pm = fmaxf(fmaxf(s_[i][0], s_[i][1]), fmaxf(s_[i][2], s_[i][3]));
            red[(ty * 4 + i) * 17 + tx] = pm;
        }
        __syncthreads();   // also guards: all KP (Kt) reads done

        if (tid < 64) {
            float m = -INFINITY;
            #pragma unroll
            for (int u = 0; u < 16; u++) m = fmaxf(m, red[tid * 17 + u]);
            float mo = mrow[tid];
            float mn = fmaxf(mo, m);
            mnew[tid] = mn;
            arow[tid] = __expf(mo - mn);
            mrow[tid] = mn;
        }
        __syncthreads();

        // P = exp(S - m), partial row sums, store P^T into KP
        float pmat[4][4];
        #pragma unroll
        for (int i = 0; i < 4; i++) {
            int r = ty * 4 + i;
            float mn = mnew[r];
            float ps = 0.0f;
            #pragma unroll
            for (int j = 0; j < 4; j++) {
                pmat[i][j] = __expf(s_[i][j] - mn);
                ps += pmat[i][j];
            }
            red[r * 17 + tx] = ps;
        }
        #pragma unroll
        for (int j = 0; j < 4; j++) {
            float4 st = make_float4(pmat[0][j], pmat[1][j], pmat[2][j], pmat[3][j]);
            *(float4*)&KP[(tx * 4 + j) * QP + ty * 4] = st;
        }
        __syncthreads();

        if (tid < 64) {
            float s = 0.0f;
            #pragma unroll
            for (int u = 0; u < 16; u++) s += red[tid * 17 + u];
            lrow[tid] = lrow[tid] * arow[tid] + s;
        }

        // O = O * alpha + P @ V
        float al[4];
        #pragma unroll
        for (int i = 0; i < 4; i++) al[i] = arow[ty * 4 + i];
        #pragma unroll
        for (int i = 0; i < 4; i++)
            #pragma unroll
            for (int j = 0; j < 4; j++)
                o[i][j] *= al[i];

        #pragma unroll 16
        for (int c = 0; c < 64; c++) {
            float4 p4 = *(const float4*)&KP[c * QP + ty * 4];
            float4 v4 = *(const float4*)&Vs[c * QP + tx * 4];
            float pa[4] = {p4.x, p4.y, p4.z, p4.w};
            float vb[4] = {v4.x, v4.y, v4.z, v4.w};
            #pragma unroll
            for (int i = 0; i < 4; i++)
                #pragma unroll
                for (int j = 0; j < 4; j++)
                    o[i][j] = fmaf(pa[i], vb[j], o[i][j]);
        }
        __syncthreads();   // before next tile overwrites KP/Vs/red
    }

    // write out: g_att[(b*1024 + q0 + r) * 768 + h*64 + col]
    int b_ = bh / Hq, h = bh % Hq;
    #pragma unroll
    for (int i = 0; i < 4; i++) {
        int r = ty * 4 + i;
        float linv = 1.0f / lrow[r];
        float4 st = make_float4(o[i][0] * linv, o[i][1] * linv,
                                o[i][2] * linv, o[i][3] * linv);
        *(float4*)&g_att[(size_t)(b_ * Nq + q0 + r) * Cq + h * 64 + tx * 4] = st;
    }
}

// =====================================================================
// GEMM 2: out = g_att @ W_proj + b_proj  (16384x768x768), double-buffered
// =====================================================================
__global__ __launch_bounds__(256) void proj_gemm(const float* __restrict__ W,
                                                 const float* __restrict__ bias,
                                                 float* __restrict__ out)
{
    __shared__ float As[2][8][128];
    __shared__ float Bs[2][8][128];
    const int K = Cq, Nn = Cq;
    int tid  = threadIdx.x;
    int rowA = tid >> 1, kA = (tid & 1) << 2;
    int kB   = tid >> 5, colB = (tid & 31) << 2;
    const float* xg = g_att + (size_t)(blockIdx.y * 128 + rowA) * K + kA;
    const float* wg = W + kB * Nn + blockIdx.x * 128 + colB;
    int ty = tid >> 4, tx = tid & 15;
    float acc[8][8] = {};

    float4 av = *(const float4*)(xg);
    float4 bv = *(const float4*)(wg);
    As[0][kA + 0][rowA] = av.x; As[0][kA + 1][rowA] = av.y;
    As[0][kA + 2][rowA] = av.z; As[0][kA + 3][rowA] = av.w;
    *(float4*)&Bs[0][kB][colB] = bv;
    __syncthreads();

    const int NCH = K / 8;   // 96
    for (int ch = 0; ch < NCH; ch++) {
        const int cur = ch & 1;
        if (ch + 1 < NCH) {
            av = *(const float4*)(xg + (ch + 1) * 8);
            bv = *(const float4*)(wg + (size_t)(ch + 1) * 8 * Nn);
        }
        #pragma unroll
        for (int k = 0; k < 8; k++) {
            float a[8], b[8];
            *(float4*)(a)     = *(const float4*)&As[cur][k][ty * 8];
            *(float4*)(a + 4) = *(const float4*)&As[cur][k][ty * 8 + 4];
            *(float4*)(b)     = *(const float4*)&Bs[cur][k][tx * 8];
            *(float4*)(b + 4) = *(const float4*)&Bs[cur][k][tx * 8 + 4];
            #pragma unroll
            for (int i = 0; i < 8; i++)
                #pragma unroll
                for (int j = 0; j < 8; j++)
                    acc[i][j] = fmaf(a[i], b[j], acc[i][j]);
        }
        if (ch + 1 < NCH) {
            const int nxt = cur ^ 1;
            As[nxt][kA + 0][rowA] = av.x; As[nxt][kA + 1][rowA] = av.y;
            As[nxt][kA + 2][rowA] = av.z; As[nxt][kA + 3][rowA] = av.w;
            *(float4*)&Bs[nxt][kB][colB] = bv;
        }
        __syncthreads();
    }

    int gm0 = blockIdx.y * 128 + ty * 8;
    int gn0 = blockIdx.x * 128 + tx * 8;
    float bi[8];
    *(float4*)(bi)     = *(const float4*)&bias[gn0];
    *(float4*)(bi + 4) = *(const float4*)&bias[gn0 + 4];
    #pragma unroll
    for (int i = 0; i < 8; i++) {
        float4 v0 = make_float4(acc[i][0] + bi[0], acc[i][1] + bi[1],
                                acc[i][2] + bi[2], acc[i][3] + bi[3]);
        float4 v1 = make_float4(acc[i][4] + bi[4], acc[i][5] + bi[5],
                                acc[i][6] + bi[6], acc[i][7] + bi[7]);
        float* row = out + (size_t)(gm0 + i) * Nn + gn0;
        *(float4*)(row)     = v0;
        *(float4*)(row + 4) = v1;
    }
}

// =====================================================================
extern "C" void kernel_launch(void* const* d_in, const int* in_sizes, int n_in,
                              void* d_out, int out_size)
{
    const float* x      = (const float*)d_in[0];
    const float* W_qkv  = (const float*)d_in[1];
    const float* b_qkv  = (const float*)d_in[2];
    const float* W_proj = (const float*)d_in[3];
    const float* b_proj = (const float*)d_in[4];
    const int*   pos_h  = (const int*)d_in[5];
    const int*   pos_w  = (const int*)d_in[6];
    float*       out    = (float*)d_out;

    cudaFuncSetAttribute(attn_kernel,
                         cudaFuncAttributeMaxDynamicSharedMemorySize,
                         (int)ATTN_SMEM);

    qkv_gemm<<<dim3(18, 128), 256>>>(x, W_qkv, b_qkv);
    rope_kernel<<<(2 * BH * Nq * 32) / 256, 256>>>(pos_h, pos_w);
    attn_kernel<<<dim3(16, 192), 256, ATTN_SMEM>>>();
    proj_gemm<<<dim3(6, 128), 256>>>(W_proj, b_proj, out);
}

// round 8
// speedup vs baseline: 1.0667x; 1.0161x over previous
#include <cuda_runtime.h>
#include <math.h>

#define Bq   16
#define Nq   1024
#define Cq   768
#define Hq   12
#define HD   64
#define BH   (Bq*Hq)        // 192
#define MROWS (Bq*Nq)       // 16384

// ---- scratch (no allocs allowed) ----
__device__ float g_q[BH * Nq * HD];     // [bh][tok][d]
__device__ float g_k[BH * Nq * HD];
__device__ float g_v[BH * Nq * HD];
__device__ float g_att[MROWS * Cq];     // [b*N + tok][h*64 + d]

// =====================================================================
// GEMM 1: qkv = x @ W_qkv + b_qkv, scattered into g_q/g_k/g_v
// 128x128x8 tile, 256 threads, 8x8 per thread. Double-buffered smem.
// (unchanged from round 7 — passing)
// =====================================================================
__global__ __launch_bounds__(256) void qkv_gemm(const float* __restrict__ x,
                                                const float* __restrict__ W,
                                                const float* __restrict__ bias)
{
    __shared__ float As[2][8][128];
    __shared__ float Bs[2][8][128];
    const int K = Cq, Nn = 3 * Cq;
    int tid  = threadIdx.x;
    int rowA = tid >> 1, kA = (tid & 1) << 2;
    int kB   = tid >> 5, colB = (tid & 31) << 2;
    const float* xg = x + (blockIdx.y * 128 + rowA) * K + kA;
    const float* wg = W + kB * Nn + blockIdx.x * 128 + colB;
    int ty = tid >> 4, tx = tid & 15;
    float acc[8][8] = {};

    float4 av = *(const float4*)(xg);
    float4 bv = *(const float4*)(wg);
    As[0][kA + 0][rowA] = av.x; As[0][kA + 1][rowA] = av.y;
    As[0][kA + 2][rowA] = av.z; As[0][kA + 3][rowA] = av.w;
    *(float4*)&Bs[0][kB][colB] = bv;
    __syncthreads();

    const int NCH = K / 8;   // 96
    for (int ch = 0; ch < NCH; ch++) {
        const int cur = ch & 1;
        if (ch + 1 < NCH) {
            av = *(const float4*)(xg + (ch + 1) * 8);
            bv = *(const float4*)(wg + (size_t)(ch + 1) * 8 * Nn);
        }
        #pragma unroll
        for (int k = 0; k < 8; k++) {
            float a[8], b[8];
            *(float4*)(a)     = *(const float4*)&As[cur][k][ty * 8];
            *(float4*)(a + 4) = *(const float4*)&As[cur][k][ty * 8 + 4];
            *(float4*)(b)     = *(const float4*)&Bs[cur][k][tx * 8];
            *(float4*)(b + 4) = *(const float4*)&Bs[cur][k][tx * 8 + 4];
            #pragma unroll
            for (int i = 0; i < 8; i++)
                #pragma unroll
                for (int j = 0; j < 8; j++)
                    acc[i][j] = fmaf(a[i], b[j], acc[i][j]);
        }
        if (ch + 1 < NCH) {
            const int nxt = cur ^ 1;
            As[nxt][kA + 0][rowA] = av.x; As[nxt][kA + 1][rowA] = av.y;
            As[nxt][kA + 2][rowA] = av.z; As[nxt][kA + 3][rowA] = av.w;
            *(float4*)&Bs[nxt][kB][colB] = bv;
        }
        __syncthreads();
    }

    int gm0 = blockIdx.y * 128 + ty * 8;
    int gn0 = blockIdx.x * 128 + tx * 8;
    #pragma unroll
    for (int i = 0; i < 8; i++) {
        int gm = gm0 + i;
        int b_ = gm >> 10, tok = gm & 1023;
        #pragma unroll
        for (int j = 0; j < 8; j++) {
            int gn = gn0 + j;
            float v = acc[i][j] + bias[gn];
            int s   = gn / Cq;
            int rem = gn - s * Cq;
            int h = rem >> 6, d = rem & 63;
            float* dst = (s == 0) ? g_q : ((s == 1) ? g_k : g_v);
            dst[((b_ * Hq + h) << 16) + (tok << 6) + d] = v;
        }
    }
}

// =====================================================================
// RoPE (in place on g_q / g_k).
// =====================================================================
__global__ void rope_kernel(const int* __restrict__ pos_h,
                            const int* __restrict__ pos_w)
{
    int idx = blockIdx.x * blockDim.x + threadIdx.x;
    int j    = idx & 15;
    int half = (idx >> 4) & 1;
    int tok  = (idx >> 5) & 1023;
    int rest = idx >> 15;           // 0..383
    if (rest >= 2 * BH) return;
    int bh   = rest % BH;
    int tens = rest / BH;           // 0=q, 1=k
    int b_ = bh / Hq;
    int pos = half ? pos_w[b_ * Nq + tok] : pos_h[b_ * Nq + tok];
    float fp = (float)pos;
    float* base = (tens ? g_k : g_q) + (bh << 16) + (tok << 6) + half * 32;
    float t0 = base[j], t1 = base[j + 16];
    float L = logf(10000.0f);
    float inv0 = expf(-(float)(j >> 1)       / 16.0f * L);
    float inv1 = expf(-(float)(8 + (j >> 1)) / 16.0f * L);
    float s0, c0, s1, c1;
    sincosf(fp * inv0, &s0, &c0);
    sincosf(fp * inv1, &s1, &c1);
    base[j]      = t0 * c0 - t1 * s0;
    base[j + 16] = t1 * c1 + t0 * s1;
}

// =====================================================================
// Flash attention: 128 q-rows x 64-key tiles, 256 threads, 8x4/thread.
// Qt[64][132] (k-major), KP[64][132] (K^T, then aliased as P^T),
// Vs[64][68], red[128][17], stats 4x128. __expf softmax.
// =====================================================================
#define QW 132
#define VW 68
#define ATTN_F (64 * QW + 64 * QW + 64 * VW + 128 * 17 + 4 * 128)
#define ATTN_SMEM (ATTN_F * sizeof(float))   // 95744 bytes

__global__ __launch_bounds__(256) void attn_kernel()
{
    extern __shared__ float sm[];
    float* Qt   = sm;                   // [k][r] 64 x 132
    float* KP   = Qt + 64 * QW;         // K^T [k][c] / P^T [c][r]
    float* Vs   = KP + 64 * QW;         // [c][j] 64 x 68
    float* red  = Vs + 64 * VW;         // [128][17]
    float* mrow = red + 128 * 17;
    float* lrow = mrow + 128;
    float* arow = lrow + 128;
    float* mnew = arow + 128;

    const int tid = threadIdx.x;
    const int bh  = blockIdx.y;
    const int q0  = blockIdx.x * 128;
    const float* Qg = g_q + ((size_t)bh << 16);
    const float* Kg = g_k + ((size_t)bh << 16);
    const float* Vg = g_v + ((size_t)bh << 16);
    const int ty = tid >> 4, tx = tid & 15;

    // load Q tile transposed
    for (int idx = tid; idx < 8192; idx += 256) {
        int r = idx >> 6, k = idx & 63;
        Qt[k * QW + r] = Qg[(q0 + r) * 64 + k];
    }
    if (tid < 128) { mrow[tid] = -INFINITY; lrow[tid] = 0.0f; }
    __syncthreads();

    float o[8][4] = {};

    for (int t = 0; t < 16; t++) {
        const int kt0 = t * 64;
        for (int idx = tid; idx < 4096; idx += 256) {
            int c = idx >> 6, k = idx & 63;
            KP[k * QW + c] = Kg[(kt0 + c) * 64 + k];
        }
        for (int idx = tid; idx < 4096; idx += 256) {
            int c = idx >> 6, j = idx & 63;
            Vs[c * VW + j] = Vg[(kt0 + c) * 64 + j];
        }
        __syncthreads();

        // S = Q @ K^T * scale   (8x4 per thread)
        float s_[8][4] = {};
        #pragma unroll 4
        for (int k = 0; k < 64; k++) {
            float a[8], b[4];
            *(float4*)(a)     = *(const float4*)&Qt[k * QW + ty * 8];
            *(float4*)(a + 4) = *(const float4*)&Qt[k * QW + ty * 8 + 4];
            *(float4*)(b)     = *(const float4*)&KP[k * QW + tx * 4];
            #pragma unroll
            for (int i = 0; i < 8; i++)
                #pragma unroll
                for (int j = 0; j < 4; j++)
                    s_[i][j] = fmaf(a[i], b[j], s_[i][j]);
        }
        #pragma unroll
        for (int i = 0; i < 8; i++) {
            float pm = -INFINITY;
            #pragma unroll
            for (int j = 0; j < 4; j++) {
                s_[i][j] *= 0.125f;
                pm = fmaxf(pm, s_[i][j]);
            }
            red[(ty * 8 + i) * 17 + tx] = pm;
        }
        __syncthreads();   // S done; KP reads done

        if (tid < 128) {
            float m = -INFINITY;
            #pragma unroll
            for (int u = 0; u < 16; u++) m = fmaxf(m, red[tid * 17 + u]);
            float mo = mrow[tid];
            float mn = fmaxf(mo, m);
            mnew[tid] = mn;
            arow[tid] = __expf(mo - mn);
            mrow[tid] = mn;
        }
        __syncthreads();

        // P = exp(S - m); partial row sums; P^T into KP
        #pragma unroll
        for (int i = 0; i < 8; i++) {
            int r = ty * 8 + i;
            float mn = mnew[r];
            float ps = 0.0f;
            #pragma unroll
            for (int j = 0; j < 4; j++) {
                float p = __expf(s_[i][j] - mn);
                s_[i][j] = p;
                ps += p;
            }
            red[r * 17 + tx] = ps;
        }
        #pragma unroll
        for (int j = 0; j < 4; j++) {
            int c = tx * 4 + j;
            *(float4*)&KP[c * QW + ty * 8] =
                make_float4(s_[0][j], s_[1][j], s_[2][j], s_[3][j]);
            *(float4*)&KP[c * QW + ty * 8 + 4] =
                make_float4(s_[4][j], s_[5][j], s_[6][j], s_[7][j]);
        }
        __syncthreads();

        if (tid < 128) {
            float s = 0.0f;
            #pragma unroll
            for (int u = 0; u < 16; u++) s += red[tid * 17 + u];
            lrow[tid] = lrow[tid] * arow[tid] + s;
        }

        // O = O*alpha + P @ V
        #pragma unroll
        for (int i = 0; i < 8; i++) {
            float al = arow[ty * 8 + i];
            #pragma unroll
            for (int j = 0; j < 4; j++) o[i][j] *= al;
        }
        #pragma unroll 4
        for (int c = 0; c < 64; c++) {
            float a[8], b[4];
            *(float4*)(a)     = *(const float4*)&KP[c * QW + ty * 8];
            *(float4*)(a + 4) = *(const float4*)&KP[c * QW + ty * 8 + 4];
            *(float4*)(b)     = *(const float4*)&Vs[c * VW + tx * 4];
            #pragma unroll
            for (int i = 0; i < 8; i++)
                #pragma unroll
                for (int j = 0; j < 4; j++)
                    o[i][j] = fmaf(a[i], b[j], o[i][j]);
        }
        __syncthreads();   // before next tile overwrites KP/Vs/red
    }

    // write out
    const int b_ = bh / Hq, h = bh % Hq;
    #pragma unroll
    for (int i = 0; i < 8; i++) {
        int r = ty * 8 + i;
        float linv = 1.0f / lrow[r];
        *(float4*)&g_att[(size_t)(b_ * Nq + q0 + r) * Cq + h * 64 + tx * 4] =
            make_float4(o[i][0] * linv, o[i][1] * linv,
                        o[i][2] * linv, o[i][3] * linv);
    }
}

// =====================================================================
// GEMM 2: out = g_att @ W_proj + b_proj  (16384x768x768), double-buffered
// (unchanged from round 7 — passing)
// =====================================================================
__global__ __launch_bounds__(256) void proj_gemm(const float* __restrict__ W,
                                                 const float* __restrict__ bias,
                                                 float* __restrict__ out)
{
    __shared__ float As[2][8][128];
    __shared__ float Bs[2][8][128];
    const int K = Cq, Nn = Cq;
    int tid  = threadIdx.x;
    int rowA = tid >> 1, kA = (tid & 1) << 2;
    int kB   = tid >> 5, colB = (tid & 31) << 2;
    const float* xg = g_att + (size_t)(blockIdx.y * 128 + rowA) * K + kA;
    const float* wg = W + kB * Nn + blockIdx.x * 128 + colB;
    int ty = tid >> 4, tx = tid & 15;
    float acc[8][8] = {};

    float4 av = *(const float4*)(xg);
    float4 bv = *(const float4*)(wg);
    As[0][kA + 0][rowA] = av.x; As[0][kA + 1][rowA] = av.y;
    As[0][kA + 2][rowA] = av.z; As[0][kA + 3][rowA] = av.w;
    *(float4*)&Bs[0][kB][colB] = bv;
    __syncthreads();

    const int NCH = K / 8;   // 96
    for (int ch = 0; ch < NCH; ch++) {
        const int cur = ch & 1;
        if (ch + 1 < NCH) {
            av = *(const float4*)(xg + (ch + 1) * 8);
            bv = *(const float4*)(wg + (size_t)(ch + 1) * 8 * Nn);
        }
        #pragma unroll
        for (int k = 0; k < 8; k++) {
            float a[8], b[8];
            *(float4*)(a)     = *(const float4*)&As[cur][k][ty * 8];
            *(float4*)(a + 4) = *(const float4*)&As[cur][k][ty * 8 + 4];
            *(float4*)(b)     = *(const float4*)&Bs[cur][k][tx * 8];
            *(float4*)(b + 4) = *(const float4*)&Bs[cur][k][tx * 8 + 4];
            #pragma unroll
            for (int i = 0; i < 8; i++)
                #pragma unroll
                for (int j = 0; j < 8; j++)
                    acc[i][j] = fmaf(a[i], b[j], acc[i][j]);
        }
        if (ch + 1 < NCH) {
            const int nxt = cur ^ 1;
            As[nxt][kA + 0][rowA] = av.x; As[nxt][kA + 1][rowA] = av.y;
            As[nxt][kA + 2][rowA] = av.z; As[nxt][kA + 3][rowA] = av.w;
            *(float4*)&Bs[nxt][kB][colB] = bv;
        }
        __syncthreads();
    }

    int gm0 = blockIdx.y * 128 + ty * 8;
    int gn0 = blockIdx.x * 128 + tx * 8;
    float bi[8];
    *(float4*)(bi)     = *(const float4*)&bias[gn0];
    *(float4*)(bi + 4) = *(const float4*)&bias[gn0 + 4];
    #pragma unroll
    for (int i = 0; i < 8; i++) {
        float4 v0 = make_float4(acc[i][0] + bi[0], acc[i][1] + bi[1],
                                acc[i][2] + bi[2], acc[i][3] + bi[3]);
        float4 v1 = make_float4(acc[i][4] + bi[4], acc[i][5] + bi[5],
                                acc[i][6] + bi[6], acc[i][7] + bi[7]);
        float* row = out + (size_t)(gm0 + i) * Nn + gn0;
        *(float4*)(row)     = v0;
        *(float4*)(row + 4) = v1;
    }
}

// =====================================================================
extern "C" void kernel_launch(void* const* d_in, const int* in_sizes, int n_in,
                              void* d_out, int out_size)
{
    const float* x      = (const float*)d_in[0];
    const float* W_qkv  = (const float*)d_in[1];
    const float* b_qkv  = (const float*)d_in[2];
    const float* W_proj = (const float*)d_in[3];
    const float* b_proj = (const float*)d_in[4];
    const int*   pos_h  = (const int*)d_in[5];
    const int*   pos_w  = (const int*)d_in[6];
    float*       out    = (float*)d_out;

    cudaFuncSetAttribute(attn_kernel,
                         cudaFuncAttributeMaxDynamicSharedMemorySize,
                         (int)ATTN_SMEM);

    qkv_gemm<<<dim3(18, 128), 256>>>(x, W_qkv, b_qkv);
    rope_kernel<<<(2 * BH * Nq * 32) / 256, 256>>>(pos_h, pos_w);
    attn_kernel<<<dim3(8, 192), 256, ATTN_SMEM>>>();
    proj_gemm<<<dim3(6, 128), 256>>>(W_proj, b_proj, out);
}

// round 9
// speedup vs baseline: 1.1909x; 1.1164x over previous
#include <cuda_runtime.h>
#include <cuda_bf16.h>
#include <mma.h>
#include <math.h>
#include <stdint.h>

using namespace nvcuda;

#define Bq   16
#define Nq   1024
#define Cq   768
#define Hq   12
#define HD   64
#define BH   (Bq*Hq)        // 192
#define MROWS (Bq*Nq)       // 16384

// ---- scratch (no allocs allowed) ----
__device__ float g_q[BH * Nq * HD];     // [bh][tok][d]
__device__ float g_k[BH * Nq * HD];
__device__ float g_v[BH * Nq * HD];
__device__ float g_att[MROWS * Cq];     // [b*N + tok][h*64 + d]

__device__ __forceinline__ void split_pack(float x0, float x1,
                                           uint32_t& hi, uint32_t& lo) {
    __nv_bfloat16 h0 = __float2bfloat16_rn(x0);
    __nv_bfloat16 h1 = __float2bfloat16_rn(x1);
    __nv_bfloat16 l0 = __float2bfloat16_rn(x0 - __bfloat162float(h0));
    __nv_bfloat16 l1 = __float2bfloat16_rn(x1 - __bfloat162float(h1));
    hi = (uint32_t)__bfloat16_as_ushort(h0) | ((uint32_t)__bfloat16_as_ushort(h1) << 16);
    lo = (uint32_t)__bfloat16_as_ushort(l0) | ((uint32_t)__bfloat16_as_ushort(l1) << 16);
}

// =====================================================================
// bf16x3 WMMA GEMM (NON-TEMPLATED — templates poison this harness).
// CTA tile 128x128, K-chunk 32, static smem 40960B.
// 8 warps = 2(m) x 4(n); warp tile 64x32 = 4x2 wmma 16x16x16 frags.
// bf16x3: hi*hi + hi*lo + lo*hi, fp32 accumulate.
// =====================================================================
#define KCH  32
#define PADK 40
#define T_M  (128 * PADK * 2)           // 10240 bytes per matrix
#define OFF_AHI 0
#define OFF_ALO (T_M)
#define OFF_BHI (2 * T_M)
#define OFF_BLO (3 * T_M)
#define MM_SMEM (4 * T_M)               // 40960 bytes static

// ---------------- GEMM 1: qkv (NN=2304), scatter epilogue --------------
__global__ __launch_bounds__(256) void qkv_wmma(const float* __restrict__ A,
                                                const float* __restrict__ W,
                                                const float* __restrict__ bias)
{
    __shared__ __align__(16) char smem[MM_SMEM];
    const int NN = 3 * Cq;
    int tid  = threadIdx.x;
    int lane = tid & 31;
    int wid  = tid >> 5;
    int wm   = wid >> 2;
    int wn   = wid & 3;

    const int m0 = blockIdx.y * 128;
    const int n0 = blockIdx.x * 128;

    wmma::fragment<wmma::accumulator, 16, 16, 16, float> acc[4][2];
    #pragma unroll
    for (int mi = 0; mi < 4; mi++)
        #pragma unroll
        for (int ni = 0; ni < 2; ni++)
            wmma::fill_fragment(acc[mi][ni], 0.0f);

    const __nv_bfloat16* Ah = (const __nv_bfloat16*)(smem + OFF_AHI);
    const __nv_bfloat16* Bh = (const __nv_bfloat16*)(smem + OFF_BHI);

    for (int ch = 0; ch < 768 / KCH; ch++) {
        const int k0c = ch * KCH;
        if (ch) __syncthreads();

        #pragma unroll
        for (int it = 0; it < 8; it++) {
            int idx = tid + it * 256;          // 0..2047
            int m  = idx >> 4;
            int kp = idx & 15;
            float2 v = *(const float2*)(A + (size_t)(m0 + m) * 768 + k0c + 2 * kp);
            uint32_t hi, lo;
            split_pack(v.x, v.y, hi, lo);
            uint32_t off = (uint32_t)(m * PADK + 2 * kp) * 2;
            *(uint32_t*)(smem + OFF_AHI + off) = hi;
            *(uint32_t*)(smem + OFF_ALO + off) = lo;
        }
        #pragma unroll
        for (int it = 0; it < 8; it++) {
            int idx = tid + it * 256;
            int n  = idx & 127;
            int kp = idx >> 7;                 // 0..15
            float w0 = W[(size_t)(k0c + 2 * kp)     * NN + n0 + n];
            float w1 = W[(size_t)(k0c + 2 * kp + 1) * NN + n0 + n];
            uint32_t hi, lo;
            split_pack(w0, w1, hi, lo);
            uint32_t off = (uint32_t)(n * PADK + 2 * kp) * 2;
            *(uint32_t*)(smem + OFF_BHI + off) = hi;
            *(uint32_t*)(smem + OFF_BLO + off) = lo;
        }
        __syncthreads();

        #pragma unroll
        for (int ks = 0; ks < 2; ks++) {
            const int kk = ks * 16;
            wmma::fragment<wmma::matrix_b, 16, 16, 16, __nv_bfloat16, wmma::col_major> fbh[2], fbl[2];
            #pragma unroll
            for (int ni = 0; ni < 2; ni++) {
                const __nv_bfloat16* bp = Bh + (wn * 32 + ni * 16) * PADK + kk;
                wmma::load_matrix_sync(fbh[ni], bp, PADK);
                wmma::load_matrix_sync(fbl[ni], bp + (T_M / 2), PADK);
            }
            #pragma unroll
            for (int mi = 0; mi < 4; mi++) {
                wmma::fragment<wmma::matrix_a, 16, 16, 16, __nv_bfloat16, wmma::row_major> fah, fal;
                const __nv_bfloat16* ap = Ah + (wm * 64 + mi * 16) * PADK + kk;
                wmma::load_matrix_sync(fah, ap, PADK);
                wmma::load_matrix_sync(fal, ap + (T_M / 2), PADK);
                #pragma unroll
                for (int ni = 0; ni < 2; ni++) {
                    wmma::mma_sync(acc[mi][ni], fah, fbh[ni], acc[mi][ni]);
                    wmma::mma_sync(acc[mi][ni], fah, fbl[ni], acc[mi][ni]);
                    wmma::mma_sync(acc[mi][ni], fal, fbh[ni], acc[mi][ni]);
                }
            }
        }
    }

    __syncthreads();
    float* patch = (float*)smem + wid * (16 * 20);
    const int r_loc = lane >> 1;
    const int c_loc = (lane & 1) * 8;

    #pragma unroll
    for (int mi = 0; mi < 4; mi++) {
        #pragma unroll
        for (int ni = 0; ni < 2; ni++) {
            wmma::store_matrix_sync(patch, acc[mi][ni], 20, wmma::mem_row_major);
            __syncwarp();
            int r  = m0 + wm * 64 + mi * 16 + r_loc;
            int cb = n0 + wn * 32 + ni * 16 + c_loc;
            float vv[8];
            #pragma unroll
            for (int j = 0; j < 8; j++)
                vv[j] = patch[r_loc * 20 + c_loc + j] + bias[cb + j];

            int b_  = r >> 10, tok = r & 1023;
            int s   = cb / Cq;
            int rem = cb - s * Cq;
            int h   = rem >> 6, d = rem & 63;
            float* dst = (s == 0) ? g_q : ((s == 1) ? g_k : g_v);
            float* dbase = dst + (((b_ * Hq + h) << 16) + (tok << 6) + d);
            #pragma unroll
            for (int j = 0; j < 8; j += 2)
                *(float2*)(dbase + j) = make_float2(vv[j], vv[j + 1]);
            __syncwarp();
        }
    }
}

// ---------------- GEMM 2: proj (NN=768), dense epilogue ----------------
__global__ __launch_bounds__(256) void proj_wmma(const float* __restrict__ W,
                                                 const float* __restrict__ bias,
                                                 float* __restrict__ out)
{
    __shared__ __align__(16) char smem[MM_SMEM];
    const int NN = Cq;
    const float* A = g_att;
    int tid  = threadIdx.x;
    int lane = tid & 31;
    int wid  = tid >> 5;
    int wm   = wid >> 2;
    int wn   = wid & 3;

    const int m0 = blockIdx.y * 128;
    const int n0 = blockIdx.x * 128;

    wmma::fragment<wmma::accumulator, 16, 16, 16, float> acc[4][2];
    #pragma unroll
    for (int mi = 0; mi < 4; mi++)
        #pragma unroll
        for (int ni = 0; ni < 2; ni++)
            wmma::fill_fragment(acc[mi][ni], 0.0f);

    const __nv_bfloat16* Ah = (const __nv_bfloat16*)(smem + OFF_AHI);
    const __nv_bfloat16* Bh = (const __nv_bfloat16*)(smem + OFF_BHI);

    for (int ch = 0; ch < 768 / KCH; ch++) {
        const int k0c = ch * KCH;
        if (ch) __syncthreads();

        #pragma unroll
        for (int it = 0; it < 8; it++) {
            int idx = tid + it * 256;
            int m  = idx >> 4;
            int kp = idx & 15;
            float2 v = *(const float2*)(A + (size_t)(m0 + m) * 768 + k0c + 2 * kp);
            uint32_t hi, lo;
            split_pack(v.x, v.y, hi, lo);
            uint32_t off = (uint32_t)(m * PADK + 2 * kp) * 2;
            *(uint32_t*)(smem + OFF_AHI + off) = hi;
            *(uint32_t*)(smem + OFF_ALO + off) = lo;
        }
        #pragma unroll
        for (int it = 0; it < 8; it++) {
            int idx = tid + it * 256;
            int n  = idx & 127;
            int kp = idx >> 7;
            float w0 = W[(size_t)(k0c + 2 * kp)     * NN + n0 + n];
            float w1 = W[(size_t)(k0c + 2 * kp + 1) * NN + n0 + n];
            uint32_t hi, lo;
            split_pack(w0, w1, hi, lo);
            uint32_t off = (uint32_t)(n * PADK + 2 * kp) * 2;
            *(uint32_t*)(smem + OFF_BHI + off) = hi;
            *(uint32_t*)(smem + OFF_BLO + off) = lo;
        }
        __syncthreads();

        #pragma unroll
        for (int ks = 0; ks < 2; ks++) {
            const int kk = ks * 16;
            wmma::fragment<wmma::matrix_b, 16, 16, 16, __nv_bfloat16, wmma::col_major> fbh[2], fbl[2];
            #pragma unroll
            for (int ni = 0; ni < 2; ni++) {
                const __nv_bfloat16* bp = Bh + (wn * 32 + ni * 16) * PADK + kk;
                wmma::load_matrix_sync(fbh[ni], bp, PADK);
                wmma::load_matrix_sync(fbl[ni], bp + (T_M / 2), PADK);
            }
            #pragma unroll
            for (int mi = 0; mi < 4; mi++) {
                wmma::fragment<wmma::matrix_a, 16, 16, 16, __nv_bfloat16, wmma::row_major> fah, fal;
                const __nv_bfloat16* ap = Ah + (wm * 64 + mi * 16) * PADK + kk;
                wmma::load_matrix_sync(fah, ap, PADK);
                wmma::load_matrix_sync(fal, ap + (T_M / 2), PADK);
                #pragma unroll
                for (int ni = 0; ni < 2; ni++) {
                    wmma::mma_sync(acc[mi][ni], fah, fbh[ni], acc[mi][ni]);
                    wmma::mma_sync(acc[mi][ni], fah, fbl[ni], acc[mi][ni]);
                    wmma::mma_sync(acc[mi][ni], fal, fbh[ni], acc[mi][ni]);
                }
            }
        }
    }

    __syncthreads();
    float* patch = (float*)smem + wid * (16 * 20);
    const int r_loc = lane >> 1;
    const int c_loc = (lane & 1) * 8;

    #pragma unroll
    for (int mi = 0; mi < 4; mi++) {
        #pragma unroll
        for (int ni = 0; ni < 2; ni++) {
            wmma::store_matrix_sync(patch, acc[mi][ni], 20, wmma::mem_row_major);
            __syncwarp();
            int r  = m0 + wm * 64 + mi * 16 + r_loc;
            int cb = n0 + wn * 32 + ni * 16 + c_loc;
            float* obase = out + (size_t)r * NN + cb;
            #pragma unroll
            for (int j = 0; j < 8; j += 2) {
                float v0 = patch[r_loc * 20 + c_loc + j]     + bias[cb + j];
                float v1 = patch[r_loc * 20 + c_loc + j + 1] + bias[cb + j + 1];
                *(float2*)(obase + j) = make_float2(v0, v1);
            }
            __syncwarp();
        }
    }
}

// =====================================================================
// RoPE (in place on g_q / g_k) — unchanged, passing.
// =====================================================================
__global__ void rope_kernel(const int* __restrict__ pos_h,
                            const int* __restrict__ pos_w)
{
    int idx = blockIdx.x * blockDim.x + threadIdx.x;
    int j    = idx & 15;
    int half = (idx >> 4) & 1;
    int tok  = (idx >> 5) & 1023;
    int rest = idx >> 15;           // 0..383
    if (rest >= 2 * BH) return;
    int bh   = rest % BH;
    int tens = rest / BH;           // 0=q, 1=k
    int b_ = bh / Hq;
    int pos = half ? pos_w[b_ * Nq + tok] : pos_h[b_ * Nq + tok];
    float fp = (float)pos;
    float* base = (tens ? g_k : g_q) + (bh << 16) + (tok << 6) + half * 32;
    float t0 = base[j], t1 = base[j + 16];
    float L = logf(10000.0f);
    float inv0 = expf(-(float)(j >> 1)       / 16.0f * L);
    float inv1 = expf(-(float)(8 + (j >> 1)) / 16.0f * L);
    float s0, c0, s1, c1;
    sincosf(fp * inv0, &s0, &c0);
    sincosf(fp * inv1, &s1, &c1);
    base[j]      = t0 * c0 - t1 * s0;
    base[j + 16] = t1 * c1 + t0 * s1;
}

// =====================================================================
// Flash attention: 128 q-rows, 8x4/thread — unchanged from round 8.
// =====================================================================
#define QW 132
#define VW 68
#define ATTN_F (64 * QW + 64 * QW + 64 * VW + 128 * 17 + 4 * 128)
#define ATTN_SMEM (ATTN_F * sizeof(float))   // 95744 bytes

__global__ __launch_bounds__(256) void attn_kernel()
{
    extern __shared__ float sm[];
    float* Qt   = sm;
    float* KP   = Qt + 64 * QW;
    float* Vs   = KP + 64 * QW;
    float* red  = Vs + 64 * VW;
    float* mrow = red + 128 * 17;
    float* lrow = mrow + 128;
    float* arow = lrow + 128;
    float* mnew = arow + 128;

    const int tid = threadIdx.x;
    const int bh  = blockIdx.y;
    const int q0  = blockIdx.x * 128;
    const float* Qg = g_q + ((size_t)bh << 16);
    const float* Kg = g_k + ((size_t)bh << 16);
    const float* Vg = g_v + ((size_t)bh << 16);
    const int ty = tid >> 4, tx = tid & 15;

    for (int idx = tid; idx < 8192; idx += 256) {
        int r = idx >> 6, k = idx & 63;
        Qt[k * QW + r] = Qg[(q0 + r) * 64 + k];
    }
    if (tid < 128) { mrow[tid] = -INFINITY; lrow[tid] = 0.0f; }
    __syncthreads();

    float o[8][4] = {};

    for (int t = 0; t < 16; t++) {
        const int kt0 = t * 64;
        for (int idx = tid; idx < 4096; idx += 256) {
            int c = idx >> 6, k = idx & 63;
            KP[k * QW + c] = Kg[(kt0 + c) * 64 + k];
        }
        for (int idx = tid; idx < 4096; idx += 256) {
            int c = idx >> 6, j = idx & 63;
            Vs[c * VW + j] = Vg[(kt0 + c) * 64 + j];
        }
        __syncthreads();

        float s_[8][4] = {};
        #pragma unroll 4
        for (int k = 0; k < 64; k++) {
            float a[8], b[4];
            *(float4*)(a)     = *(const float4*)&Qt[k * QW + ty * 8];
            *(float4*)(a + 4) = *(const float4*)&Qt[k * QW + ty * 8 + 4];
            *(float4*)(b)     = *(const float4*)&KP[k * QW + tx * 4];
            #pragma unroll
            for (int i = 0; i < 8; i++)
                #pragma unroll
                for (int j = 0; j < 4; j++)
                    s_[i][j] = fmaf(a[i], b[j], s_[i][j]);
        }
        #pragma unroll
        for (int i = 0; i < 8; i++) {
            float pm = -INFINITY;
            #pragma unroll
            for (int j = 0; j < 4; j++) {
                s_[i][j] *= 0.125f;
                pm = fmaxf(pm, s_[i][j]);
            }
            red[(ty * 8 + i) * 17 + tx] = pm;
        }
        __syncthreads();

        if (tid < 128) {
            float m = -INFINITY;
            #pragma unroll
            for (int u = 0; u < 16; u++) m = fmaxf(m, red[tid * 17 + u]);
            float mo = mrow[tid];
            float mn = fmaxf(mo, m);
            mnew[tid] = mn;
            arow[tid] = __expf(mo - mn);
            mrow[tid] = mn;
        }
        __syncthreads();

        #pragma unroll
        for (int i = 0; i < 8; i++) {
            int r = ty * 8 + i;
            float mn = mnew[r];
            float ps = 0.0f;
            #pragma unroll
            for (int j = 0; j < 4; j++) {
                float p = __expf(s_[i][j] - mn);
                s_[i][j] = p;
                ps += p;
            }
            red[r * 17 + tx] = ps;
        }
        #pragma unroll
        for (int j = 0; j < 4; j++) {
            int c = tx * 4 + j;
            *(float4*)&KP[c * QW + ty * 8] =
                make_float4(s_[0][j], s_[1][j], s_[2][j], s_[3][j]);
            *(float4*)&KP[c * QW + ty * 8 + 4] =
                make_float4(s_[4][j], s_[5][j], s_[6][j], s_[7][j]);
        }
        __syncthreads();

        if (tid < 128) {
            float s = 0.0f;
            #pragma unroll
            for (int u = 0; u < 16; u++) s += red[tid * 17 + u];
            lrow[tid] = lrow[tid] * arow[tid] + s;
        }

        #pragma unroll
        for (int i = 0; i < 8; i++) {
            float al = arow[ty * 8 + i];
            #pragma unroll
            for (int j = 0; j < 4; j++) o[i][j] *= al;
        }
        #pragma unroll 4
        for (int c = 0; c < 64; c++) {
            float a[8], b[4];
            *(float4*)(a)     = *(const float4*)&KP[c * QW + ty * 8];
            *(float4*)(a + 4) = *(const float4*)&KP[c * QW + ty * 8 + 4];
            *(float4*)(b)     = *(const float4*)&Vs[c * VW + tx * 4];
            #pragma unroll
            for (int i = 0; i < 8; i++)
                #pragma unroll
                for (int j = 0; j < 4; j++)
                    o[i][j] = fmaf(a[i], b[j], o[i][j]);
        }
        __syncthreads();
    }

    const int b_ = bh / Hq, h = bh % Hq;
    #pragma unroll
    for (int i = 0; i < 8; i++) {
        int r = ty * 8 + i;
        float linv = 1.0f / lrow[r];
        *(float4*)&g_att[(size_t)(b_ * Nq + q0 + r) * Cq + h * 64 + tx * 4] =
            make_float4(o[i][0] * linv, o[i][1] * linv,
                        o[i][2] * linv, o[i][3] * linv);
    }
}

// =====================================================================
extern "C" void kernel_launch(void* const* d_in, const int* in_sizes, int n_in,
                              void* d_out, int out_size)
{
    const float* x      = (const float*)d_in[0];
    const float* W_qkv  = (const float*)d_in[1];
    const float* b_qkv  = (const float*)d_in[2];
    const float* W_proj = (const float*)d_in[3];
    const float* b_proj = (const float*)d_in[4];
    const int*   pos_h  = (const int*)d_in[5];
    const int*   pos_w  = (const int*)d_in[6];
    float*       out    = (float*)d_out;

    cudaFuncSetAttribute(attn_kernel,
                         cudaFuncAttributeMaxDynamicSharedMemorySize,
                         (int)ATTN_SMEM);

    qkv_wmma<<<dim3(18, 128), 256>>>(x, W_qkv, b_qkv);
    rope_kernel<<<(2 * BH * Nq * 32) / 256, 256>>>(pos_h, pos_w);
    attn_kernel<<<dim3(8, 192), 256, ATTN_SMEM>>>();
    proj_wmma<<<dim3(6, 128), 256>>>(W_proj, b_proj, out);
}